// round 16
// baseline (speedup 1.0000x reference)
#include <cuda_runtime.h>
#include <math.h>

#define TT  512
#define BB  64
#define DIN 512
#define HH  1024
// BETA = 1.0f folded into proj epilogue as shift

// ---------------- device scratch (no runtime allocation allowed) ----------------
static __device__ __align__(16) float g_Pf[(size_t)TT * BB * HH];   // 134 MB
static __device__ __align__(16) float g_Pg[(size_t)TT * BB * HH];   // 134 MB
static __device__ __align__(16) float g_Y0[(size_t)TT * BB * HH];   // 134 MB
static __device__ __align__(16) float g_h[2][BB * HH];              // ping-pong h
static __device__ unsigned g_count;                                 // grid barrier counter

// ---------------- reset hidden state + barrier counter ----------------
__global__ void reset_kernel() {
    int i = blockIdx.x * blockDim.x + threadIdx.x;   // grid covers exactly BB*HH
    g_h[0][i] = 0.0f;
    g_h[1][i] = 0.0f;
    if (i == 0) g_count = 0u;
}

// ---------------- projection GEMM: Out[m,n] = sum_k X[m,k]*W[n,k] + b[n] (+shift) ----------------
// M = TT*BB, N = HH, K = din. Tile 64x64x32, 256 threads, 4x4 register blocking.
// blockIdx.z selects gate (0 = f -> g_Pf with -BETA, 1 = g -> g_Pg).
__global__ __launch_bounds__(256) void proj_kernel(
    const float* __restrict__ Xext, int layer, int K,
    const float* __restrict__ Wf, const float* __restrict__ bf,
    const float* __restrict__ Wg, const float* __restrict__ bg)
{
    const float* __restrict__ X = (layer == 0) ? Xext : g_Y0;
    const int gate = blockIdx.z;
    const float* __restrict__ W    = gate ? Wg : Wf;
    const float* __restrict__ bias = gate ? bg : bf;
    const float shift = gate ? 0.0f : -1.0f;           // -BETA on the f gate
    float* __restrict__ Out = gate ? g_Pg : g_Pf;

    __shared__ __align__(16) float As[32][68];   // [k][m], pad 68 keeps float4 alignment
    __shared__ __align__(16) float Bs[32][68];   // [k][n]

    const int m0 = blockIdx.y * 64;
    const int n0 = blockIdx.x * 64;
    const int tid = threadIdx.x;
    const int tx = tid & 15;        // n sub-tile
    const int ty = tid >> 4;        // m sub-tile
    const int lrow = tid >> 5;      // 0..7
    const int lcol = tid & 31;      // 0..31

    float acc[4][4];
#pragma unroll
    for (int i = 0; i < 4; i++)
#pragma unroll
        for (int j = 0; j < 4; j++) acc[i][j] = 0.0f;

    for (int k0 = 0; k0 < K; k0 += 32) {
#pragma unroll
        for (int it = 0; it < 8; it++) {
            int r = lrow + it * 8;
            As[lcol][r] = X[(size_t)(m0 + r) * K + k0 + lcol];
            Bs[lcol][r] = W[(size_t)(n0 + r) * K + k0 + lcol];
        }
        __syncthreads();
#pragma unroll
        for (int kk = 0; kk < 32; kk++) {
            float4 a4 = *(const float4*)&As[kk][ty * 4];
            float4 b4 = *(const float4*)&Bs[kk][tx * 4];
            float av[4] = {a4.x, a4.y, a4.z, a4.w};
            float bv[4] = {b4.x, b4.y, b4.z, b4.w};
#pragma unroll
            for (int i = 0; i < 4; i++)
#pragma unroll
                for (int j = 0; j < 4; j++) acc[i][j] += av[i] * bv[j];
        }
        __syncthreads();
    }

    float4 bi4 = *(const float4*)&bias[n0 + tx * 4];
    float bv[4] = {bi4.x, bi4.y, bi4.z, bi4.w};
#pragma unroll
    for (int i = 0; i < 4; i++) {
        int m = m0 + ty * 4 + i;
        float4 o;
        o.x = acc[i][0] + bv[0] + shift;
        o.y = acc[i][1] + bv[1] + shift;
        o.z = acc[i][2] + bv[2] + shift;
        o.w = acc[i][3] + bv[3] + shift;
        *(float4*)&Out[(size_t)m * HH + n0 + tx * 4] = o;
    }
}

// ---------------- persistent recurrence scan: all 512 steps in ONE kernel ----------------
// grid = 128 CTAs (all co-resident: 1 CTA/SM due to ~145KB smem, 128 <= 148 SMs).
// blockIdx.x & 1 -> b-half (32 rows), blockIdx.x >> 1 -> j-tile of 16.
// 256 threads: tid>>7 = gate, (tid&127)>>4 = jg (2 j cols), tid&15 = bg (rows bg, bg+16).
// Recurrent weights (both gates, 16 rows x 1024, padded 1028) preloaded into smem ONCE.
// Per step: GEMM K=1024 chunked by 32, double-buffered h tile (XOR swizzle), fused
// gate activations + state update + Y write, then software grid barrier.
#define WPAD 1028
#define SCAN_SMEM ((2*16*WPAD + 2*32*36 + 2*16*32) * sizeof(float))

__global__ __launch_bounds__(256) void scan_kernel(
    int layer,
    const float* __restrict__ hfW, const float* __restrict__ hfB,
    const float* __restrict__ hgW, const float* __restrict__ hgB,
    float* __restrict__ OutFinal)
{
    extern __shared__ float smem[];
    float* Wsm  = smem;                        // [2][16][WPAD]
    float* Hsm  = smem + 2*16*WPAD;            // [2][32][36]  (double buffer, swizzled)
    float* FGsm = Hsm + 2*32*36;               // [2][16][32]  gate pre-activations

    const int tid = threadIdx.x;
    const int g   = tid >> 7;          // gate
    const int t2  = tid & 127;
    const int jg  = t2 >> 4;           // 0..7 -> columns jg*2, jg*2+1
    const int bg  = t2 & 15;           // rows bg, bg+16
    const int b0  = (blockIdx.x & 1) * 32;
    const int j0  = (blockIdx.x >> 1) * 16;

    float* __restrict__ Y = (layer == 0) ? g_Y0 : OutFinal;

    // ---- one-time W preload (both gates) into smem ----
    {
        const float* __restrict__ Wsrc = g ? hgW : hfW;
#pragma unroll
        for (int r = 0; r < 16; r++) {
            float4 v0 = *(const float4*)&Wsrc[(size_t)(j0 + r) * HH + t2 * 8];
            float4 v1 = *(const float4*)&Wsrc[(size_t)(j0 + r) * HH + t2 * 8 + 4];
            *(float4*)&Wsm[(g * 16 + r) * WPAD + t2 * 8]     = v0;
            *(float4*)&Wsm[(g * 16 + r) * WPAD + t2 * 8 + 4] = v1;
        }
    }
    const float* __restrict__ bsel = g ? hgB : hfB;
    const float bj0 = bsel[j0 + jg * 2 + 0];
    const float bj1 = bsel[j0 + jg * 2 + 1];

    // per-thread h-load indices
    const int hb   = tid >> 3;                  // 0..31 (row within b-half)
    const int hk4  = tid & 7;                   // float4 index within 32-k chunk
    const int hk4s = hk4 ^ ((hb >> 3) & 1);     // store swizzle
    const int swz  = (bg >> 3) & 1;             // matching read swizzle

    const float* __restrict__ W0 = &Wsm[(g * 16 + jg * 2 + 0) * WPAD];
    const float* __restrict__ W1 = &Wsm[(g * 16 + jg * 2 + 1) * WPAD];

    __syncthreads();

    for (int t = 0; t < TT; t++) {
        const float* __restrict__ hp = g_h[t & 1];
        float* __restrict__ hn = g_h[(t & 1) ^ 1];

        float acc00 = 0.f, acc01 = 0.f, acc10 = 0.f, acc11 = 0.f;

        // preload chunk 0 (L2-coherent loads: h is written by other SMs)
        {
            float4 v = __ldcg((const float4*)&hp[(b0 + hb) * HH + hk4 * 4]);
            *(float4*)&Hsm[(0 * 32 + hb) * 36 + hk4s * 4] = v;
        }
        __syncthreads();

        for (int c = 0; c < 32; c++) {
            const int cur = c & 1;
            float4 hreg;
            if (c + 1 < 32)
                hreg = __ldcg((const float4*)&hp[(b0 + hb) * HH + (c + 1) * 32 + hk4 * 4]);

            const float* __restrict__ Hb = &Hsm[cur * 32 * 36];
#pragma unroll
            for (int kq = 0; kq < 8; kq++) {
                const int kqs = kq ^ swz;
                float4 h0 = *(const float4*)&Hb[bg * 36 + kqs * 4];
                float4 h1 = *(const float4*)&Hb[(bg + 16) * 36 + kqs * 4];
                float4 w0 = *(const float4*)&W0[c * 32 + kq * 4];
                float4 w1 = *(const float4*)&W1[c * 32 + kq * 4];
                acc00 += h0.x * w0.x + h0.y * w0.y + h0.z * w0.z + h0.w * w0.w;
                acc01 += h0.x * w1.x + h0.y * w1.y + h0.z * w1.z + h0.w * w1.w;
                acc10 += h1.x * w0.x + h1.y * w0.y + h1.z * w0.z + h1.w * w0.w;
                acc11 += h1.x * w1.x + h1.y * w1.y + h1.z * w1.z + h1.w * w1.w;
            }
            if (c + 1 < 32) {
                const int nxt = cur ^ 1;
                *(float4*)&Hsm[(nxt * 32 + hb) * 36 + hk4s * 4] = hreg;
            }
            __syncthreads();
        }

        // stash pre-activations (with recurrent bias) so update threads see both gates
        FGsm[(g * 16 + jg * 2 + 0) * 32 + bg]      = acc00 + bj0;
        FGsm[(g * 16 + jg * 2 + 1) * 32 + bg]      = acc01 + bj1;
        FGsm[(g * 16 + jg * 2 + 0) * 32 + bg + 16] = acc10 + bj0;
        FGsm[(g * 16 + jg * 2 + 1) * 32 + bg + 16] = acc11 + bj1;
        __syncthreads();

        // fused gate nonlinearities + state update + output write (512 outputs, 2/thread)
#pragma unroll
        for (int u = 0; u < 2; u++) {
            int idx = tid + u * 256;
            int jj  = idx & 15;
            int bl  = idx >> 4;            // 0..31
            int b   = b0 + bl;
            int j   = j0 + jj;
            size_t off = ((size_t)t * BB + b) * HH + j;
            float F = 1.0f / (1.0f + expf(-(FGsm[(0 * 16 + jj) * 32 + bl] + g_Pf[off])));
            float G = tanhf(FGsm[(1 * 16 + jj) * 32 + bl] + g_Pg[off]);
            float hpv = __ldcg(&hp[b * HH + j]);
            float hnv = F * hpv + (1.0f - F) * G;
            hn[b * HH + j] = hnv;
            Y[off] = hnv;
        }

        // ---- software grid barrier (all 128 CTAs co-resident) ----
        __syncthreads();
        if (tid == 0) {
            __threadfence();                       // h_next/Y visible at L2 before arrive
            atomicAdd(&g_count, 1u);
            const unsigned goal = (unsigned)(t + 1) * gridDim.x;
            while (*(volatile unsigned*)&g_count < goal) { }
            __threadfence();
        }
        __syncthreads();
    }
}

// ---------------- launch ----------------
extern "C" void kernel_launch(void* const* d_in, const int* in_sizes, int n_in,
                              void* d_out, int out_size)
{
    const float* X    = (const float*)d_in[0];
    const float* ifW0 = (const float*)d_in[1];
    const float* ifB0 = (const float*)d_in[2];
    const float* hfW0 = (const float*)d_in[3];
    const float* hfB0 = (const float*)d_in[4];
    const float* igW0 = (const float*)d_in[5];
    const float* igB0 = (const float*)d_in[6];
    const float* hgW0 = (const float*)d_in[7];
    const float* hgB0 = (const float*)d_in[8];
    const float* ifW1 = (const float*)d_in[9];
    const float* ifB1 = (const float*)d_in[10];
    const float* hfW1 = (const float*)d_in[11];
    const float* hfB1 = (const float*)d_in[12];
    const float* igW1 = (const float*)d_in[13];
    const float* igB1 = (const float*)d_in[14];
    const float* hgW1 = (const float*)d_in[15];
    const float* hgB1 = (const float*)d_in[16];
    float* out = (float*)d_out;

    static int smem_set = 0;
    if (!smem_set) {
        cudaFuncSetAttribute(scan_kernel,
                             cudaFuncAttributeMaxDynamicSharedMemorySize,
                             (int)SCAN_SMEM);
        smem_set = 1;
    }

    dim3 pjGrid(HH / 64, (TT * BB) / 64, 2);

    // ---- layer 0 ----
    reset_kernel<<<256, 256>>>();
    proj_kernel<<<pjGrid, 256>>>(X, 0, DIN, ifW0, ifB0, igW0, igB0);
    scan_kernel<<<128, 256, SCAN_SMEM>>>(0, hfW0, hfB0, hgW0, hgB0, out);

    // ---- layer 1 (input = g_Y0 written by layer-0 scan) ----
    proj_kernel<<<pjGrid, 256>>>(X, 1, HH, ifW1, ifB1, igW1, igB1);
    reset_kernel<<<256, 256>>>();
    scan_kernel<<<128, 256, SCAN_SMEM>>>(1, hfW1, hfB1, hgW1, hgB1, out);
}

// round 17
// speedup vs baseline: 1.1913x; 1.1913x over previous
#include <cuda_runtime.h>
#include <math.h>

#define TT  512
#define BB  64
#define DIN 512
#define HH  1024
// BETA = 1.0f folded into proj epilogue as shift

// ---------------- device scratch (no runtime allocation allowed) ----------------
static __device__ __align__(16) float g_Pf[(size_t)TT * BB * HH];   // 134 MB
static __device__ __align__(16) float g_Pg[(size_t)TT * BB * HH];   // 134 MB
static __device__ __align__(16) float g_Y0[(size_t)TT * BB * HH];   // 134 MB
static __device__ __align__(16) float g_h[2][BB * HH];              // ping-pong h
static __device__ unsigned g_count;                                 // grid barrier counter

// ---------------- reset hidden state + barrier counter ----------------
__global__ void reset_kernel() {
    int i = blockIdx.x * blockDim.x + threadIdx.x;   // grid covers exactly BB*HH
    g_h[0][i] = 0.0f;
    g_h[1][i] = 0.0f;
    if (i == 0) g_count = 0u;
}

// ---------------- projection GEMM: Out[m,n] = sum_k X[m,k]*W[n,k] + b[n] (+shift) ----
// M = TT*BB, N = HH, K = din. 128x128 tile, k-chunk 8, 256 threads, 8x8 microtile,
// double-buffered smem. blockIdx.z selects gate (0 = f -> g_Pf with -BETA, 1 = g).
__global__ __launch_bounds__(256, 2) void proj_kernel(
    const float* __restrict__ Xext, int layer, int K,
    const float* __restrict__ Wf, const float* __restrict__ bf,
    const float* __restrict__ Wg, const float* __restrict__ bg)
{
    const float* __restrict__ X = (layer == 0) ? Xext : g_Y0;
    const int gate = blockIdx.z;
    const float* __restrict__ W    = gate ? Wg : Wf;
    const float* __restrict__ bias = gate ? bg : bf;
    const float shift = gate ? 0.0f : -1.0f;           // -BETA on the f gate
    float* __restrict__ Out = gate ? g_Pg : g_Pf;

    __shared__ __align__(16) float As[2][8][132];      // [buf][k][m]
    __shared__ __align__(16) float Bs[2][8][132];      // [buf][k][n]

    const int m0 = blockIdx.y * 128;
    const int n0 = blockIdx.x * 128;
    const int tid = threadIdx.x;
    const int tx = tid & 15;          // n micro index
    const int ty = tid >> 4;          // m micro index
    const int lrow = tid >> 1;        // 0..127: row loaded by this thread
    const int lkq  = tid & 1;         // which float4 of the 8-k chunk

    const float* Ab = X + (size_t)(m0 + lrow) * K + lkq * 4;
    const float* Bb = W + (size_t)(n0 + lrow) * K + lkq * 4;

    float acc[8][8];
#pragma unroll
    for (int i = 0; i < 8; i++)
#pragma unroll
        for (int j = 0; j < 8; j++) acc[i][j] = 0.0f;

    const int nc = K / 8;

    // prime chunk 0
    {
        float4 a = *(const float4*)Ab;
        float4 b = *(const float4*)Bb;
        As[0][lkq * 4 + 0][lrow] = a.x;  As[0][lkq * 4 + 1][lrow] = a.y;
        As[0][lkq * 4 + 2][lrow] = a.z;  As[0][lkq * 4 + 3][lrow] = a.w;
        Bs[0][lkq * 4 + 0][lrow] = b.x;  Bs[0][lkq * 4 + 1][lrow] = b.y;
        Bs[0][lkq * 4 + 2][lrow] = b.z;  Bs[0][lkq * 4 + 3][lrow] = b.w;
    }
    __syncthreads();

    for (int c = 0; c < nc; c++) {
        const int cur = c & 1;
        float4 an, bn;
        if (c + 1 < nc) {
            an = *(const float4*)(Ab + (c + 1) * 8);
            bn = *(const float4*)(Bb + (c + 1) * 8);
        }
#pragma unroll
        for (int kk = 0; kk < 8; kk++) {
            float4 a0 = *(const float4*)&As[cur][kk][ty * 4];
            float4 a1 = *(const float4*)&As[cur][kk][64 + ty * 4];
            float4 b0 = *(const float4*)&Bs[cur][kk][tx * 4];
            float4 b1 = *(const float4*)&Bs[cur][kk][64 + tx * 4];
            float av[8] = {a0.x, a0.y, a0.z, a0.w, a1.x, a1.y, a1.z, a1.w};
            float bv[8] = {b0.x, b0.y, b0.z, b0.w, b1.x, b1.y, b1.z, b1.w};
#pragma unroll
            for (int i = 0; i < 8; i++)
#pragma unroll
                for (int j = 0; j < 8; j++) acc[i][j] += av[i] * bv[j];
        }
        if (c + 1 < nc) {
            const int nxt = cur ^ 1;
            As[nxt][lkq * 4 + 0][lrow] = an.x;  As[nxt][lkq * 4 + 1][lrow] = an.y;
            As[nxt][lkq * 4 + 2][lrow] = an.z;  As[nxt][lkq * 4 + 3][lrow] = an.w;
            Bs[nxt][lkq * 4 + 0][lrow] = bn.x;  Bs[nxt][lkq * 4 + 1][lrow] = bn.y;
            Bs[nxt][lkq * 4 + 2][lrow] = bn.z;  Bs[nxt][lkq * 4 + 3][lrow] = bn.w;
        }
        __syncthreads();
    }

    // epilogue: bias (+shift) and 16 float4 stores
    float4 bi0 = *(const float4*)&bias[n0 + tx * 4];
    float4 bi1 = *(const float4*)&bias[n0 + 64 + tx * 4];
    float bv[8] = {bi0.x + shift, bi0.y + shift, bi0.z + shift, bi0.w + shift,
                   bi1.x + shift, bi1.y + shift, bi1.z + shift, bi1.w + shift};
#pragma unroll
    for (int ih = 0; ih < 2; ih++) {
#pragma unroll
        for (int r = 0; r < 4; r++) {
            const int i = ih * 4 + r;
            const int m = m0 + ih * 64 + ty * 4 + r;
            float4 o0, o1;
            o0.x = acc[i][0] + bv[0];  o0.y = acc[i][1] + bv[1];
            o0.z = acc[i][2] + bv[2];  o0.w = acc[i][3] + bv[3];
            o1.x = acc[i][4] + bv[4];  o1.y = acc[i][5] + bv[5];
            o1.z = acc[i][6] + bv[6];  o1.w = acc[i][7] + bv[7];
            *(float4*)&Out[(size_t)m * HH + n0 + tx * 4]      = o0;
            *(float4*)&Out[(size_t)m * HH + n0 + 64 + tx * 4] = o1;
        }
    }
}

// ---------------- persistent recurrence scan: all 512 steps in ONE kernel ----------------
// grid = 128 CTAs (all co-resident: 1 CTA/SM, ~141KB smem). 256 threads = 8 warps.
// blockIdx.x & 1 -> b-half (32 rows), blockIdx.x >> 1 -> j-tile of 16.
// Warp w -> 4 columns {w*4..w*4+3} of 32 cols (col = gate*16 + j); lane l -> b-row l.
// W reads are warp-BROADCAST (all lanes same address -> 1 wavefront); h reads are one
// conflict-free LDS.128 per lane feeding 16 FFMA -> smem crossbar no longer binding.
// W (both gates, 16 rows x 1024) preloaded to smem once; h streamed in 32-k chunks,
// double buffered. Pointwise operands (Pf/Pg/h) prefetched before the GEMM.
#define SCAN_SMEM ((32*1024 + 2*32*36 + 32*33) * sizeof(float))

__global__ __launch_bounds__(256) void scan_kernel(
    int layer,
    const float* __restrict__ hfW, const float* __restrict__ hfB,
    const float* __restrict__ hgW, const float* __restrict__ hgB,
    float* __restrict__ OutFinal)
{
    extern __shared__ float smem[];
    float* Wsm  = smem;                        // [32 cols][1024 k]
    float* Hsm  = smem + 32 * 1024;            // [2][32 b][36]  (double buffer)
    float* FGsm = Hsm + 2 * 32 * 36;           // [32 cols][33]  pre-activations

    const int tid  = threadIdx.x;
    const int lane = tid & 31;         // b-row within b-half
    const int w    = tid >> 5;         // warp -> 4 cols
    const int b0   = (blockIdx.x & 1) * 32;
    const int j0   = (blockIdx.x >> 1) * 16;

    float* __restrict__ Y = (layer == 0) ? g_Y0 : OutFinal;

    // ---- one-time W preload (both gates) into smem, col-major rows ----
    {
        const int g  = tid >> 7;
        const int t2 = tid & 127;
        const float* __restrict__ Wsrc = g ? hgW : hfW;
#pragma unroll
        for (int r = 0; r < 16; r++) {
            float4 v0 = *(const float4*)&Wsrc[(size_t)(j0 + r) * HH + t2 * 8];
            float4 v1 = *(const float4*)&Wsrc[(size_t)(j0 + r) * HH + t2 * 8 + 4];
            *(float4*)&Wsm[(g * 16 + r) * 1024 + t2 * 8]     = v0;
            *(float4*)&Wsm[(g * 16 + r) * 1024 + t2 * 8 + 4] = v1;
        }
    }

    // bias for this warp's 4 columns
    const int gate = w >> 2;
    const float* __restrict__ bsel = gate ? hgB : hfB;
    float bj[4];
#pragma unroll
    for (int cc = 0; cc < 4; cc++) bj[cc] = bsel[j0 + (w & 3) * 4 + cc];

    // h staging indices (256 threads load 32x32 chunk: 1 float4 each)
    const int hb  = tid >> 3;          // 0..31
    const int hk4 = tid & 7;           // 0..7

    // update-phase indices: 512 outputs, 2 per thread; j fast for coalescing
    int ub[2], ujj[2];
#pragma unroll
    for (int u = 0; u < 2; u++) {
        int idx = tid + u * 256;
        ub[u]  = idx >> 4;             // 0..31 (b local)
        ujj[u] = idx & 15;             // 0..15 (j local)
    }

    const float* __restrict__ Wp0 = &Wsm[(w * 4 + 0) * 1024];
    const float* __restrict__ Wp1 = &Wsm[(w * 4 + 1) * 1024];
    const float* __restrict__ Wp2 = &Wsm[(w * 4 + 2) * 1024];
    const float* __restrict__ Wp3 = &Wsm[(w * 4 + 3) * 1024];

    __syncthreads();

    for (int t = 0; t < TT; t++) {
        const float* __restrict__ hp = g_h[t & 1];
        float* __restrict__ hn = g_h[(t & 1) ^ 1];

        // prefetch pointwise operands for this step (hides L2 latency behind GEMM)
        float pf[2], pg[2], hpv[2];
#pragma unroll
        for (int u = 0; u < 2; u++) {
            size_t off = ((size_t)t * BB + b0 + ub[u]) * HH + j0 + ujj[u];
            pf[u]  = __ldcg(&g_Pf[off]);
            pg[u]  = __ldcg(&g_Pg[off]);
            hpv[u] = __ldcg(&hp[(b0 + ub[u]) * HH + j0 + ujj[u]]);
        }

        float acc0 = 0.f, acc1 = 0.f, acc2 = 0.f, acc3 = 0.f;

        // stage chunk 0 (L2-coherent: h written by other SMs)
        {
            float4 v = __ldcg((const float4*)&hp[(b0 + hb) * HH + hk4 * 4]);
            *(float4*)&Hsm[(0 * 32 + hb) * 36 + hk4 * 4] = v;
        }
        __syncthreads();

        for (int c = 0; c < 32; c++) {
            const int cur = c & 1;
            float4 hreg;
            if (c + 1 < 32)
                hreg = __ldcg((const float4*)&hp[(b0 + hb) * HH + (c + 1) * 32 + hk4 * 4]);

            const float* __restrict__ Hb = &Hsm[cur * 32 * 36 + lane * 36];
#pragma unroll
            for (int kq = 0; kq < 8; kq++) {
                float4 h4 = *(const float4*)&Hb[kq * 4];
                float4 w0 = *(const float4*)&Wp0[c * 32 + kq * 4];   // broadcast
                float4 w1 = *(const float4*)&Wp1[c * 32 + kq * 4];
                float4 w2 = *(const float4*)&Wp2[c * 32 + kq * 4];
                float4 w3 = *(const float4*)&Wp3[c * 32 + kq * 4];
                acc0 += h4.x * w0.x + h4.y * w0.y + h4.z * w0.z + h4.w * w0.w;
                acc1 += h4.x * w1.x + h4.y * w1.y + h4.z * w1.z + h4.w * w1.w;
                acc2 += h4.x * w2.x + h4.y * w2.y + h4.z * w2.z + h4.w * w2.w;
                acc3 += h4.x * w3.x + h4.y * w3.y + h4.z * w3.z + h4.w * w3.w;
            }
            if (c + 1 < 32)
                *(float4*)&Hsm[((cur ^ 1) * 32 + hb) * 36 + hk4 * 4] = hreg;
            __syncthreads();
        }

        // stash pre-activations (with recurrent bias): FGsm[col][b], pad 33
        FGsm[(w * 4 + 0) * 33 + lane] = acc0 + bj[0];
        FGsm[(w * 4 + 1) * 33 + lane] = acc1 + bj[1];
        FGsm[(w * 4 + 2) * 33 + lane] = acc2 + bj[2];
        FGsm[(w * 4 + 3) * 33 + lane] = acc3 + bj[3];
        __syncthreads();

        // fused gate nonlinearities + state update + output write
#pragma unroll
        for (int u = 0; u < 2; u++) {
            float F = 1.0f / (1.0f + expf(-(FGsm[ujj[u] * 33 + ub[u]] + pf[u])));
            float G = tanhf(FGsm[(16 + ujj[u]) * 33 + ub[u]] + pg[u]);
            float hnv = F * hpv[u] + (1.0f - F) * G;
            size_t off = ((size_t)t * BB + b0 + ub[u]) * HH + j0 + ujj[u];
            hn[(b0 + ub[u]) * HH + j0 + ujj[u]] = hnv;
            Y[off] = hnv;
        }

        // ---- software grid barrier (all 128 CTAs co-resident) ----
        __syncthreads();
        if (tid == 0) {
            __threadfence();                       // h_next/Y visible at L2 before arrive
            atomicAdd(&g_count, 1u);
            const unsigned goal = (unsigned)(t + 1) * gridDim.x;
            while (*(volatile unsigned*)&g_count < goal) { }
            __threadfence();
        }
        __syncthreads();
    }
}

// ---------------- launch ----------------
extern "C" void kernel_launch(void* const* d_in, const int* in_sizes, int n_in,
                              void* d_out, int out_size)
{
    const float* X    = (const float*)d_in[0];
    const float* ifW0 = (const float*)d_in[1];
    const float* ifB0 = (const float*)d_in[2];
    const float* hfW0 = (const float*)d_in[3];
    const float* hfB0 = (const float*)d_in[4];
    const float* igW0 = (const float*)d_in[5];
    const float* igB0 = (const float*)d_in[6];
    const float* hgW0 = (const float*)d_in[7];
    const float* hgB0 = (const float*)d_in[8];
    const float* ifW1 = (const float*)d_in[9];
    const float* ifB1 = (const float*)d_in[10];
    const float* hfW1 = (const float*)d_in[11];
    const float* hfB1 = (const float*)d_in[12];
    const float* igW1 = (const float*)d_in[13];
    const float* igB1 = (const float*)d_in[14];
    const float* hgW1 = (const float*)d_in[15];
    const float* hgB1 = (const float*)d_in[16];
    float* out = (float*)d_out;

    static int smem_set = 0;
    if (!smem_set) {
        cudaFuncSetAttribute(scan_kernel,
                             cudaFuncAttributeMaxDynamicSharedMemorySize,
                             (int)SCAN_SMEM);
        smem_set = 1;
    }

    dim3 pjGrid(HH / 128, (TT * BB) / 128, 2);

    // ---- layer 0 ----
    reset_kernel<<<256, 256>>>();
    proj_kernel<<<pjGrid, 256>>>(X, 0, DIN, ifW0, ifB0, igW0, igB0);
    scan_kernel<<<128, 256, SCAN_SMEM>>>(0, hfW0, hfB0, hgW0, hgB0, out);

    // ---- layer 1 (input = g_Y0 written by layer-0 scan) ----
    proj_kernel<<<pjGrid, 256>>>(X, 1, HH, ifW1, ifB1, igW1, igB1);
    reset_kernel<<<256, 256>>>();
    scan_kernel<<<128, 256, SCAN_SMEM>>>(1, hfW1, hfB1, hgW1, hgB1, out);
}